// round 6
// baseline (speedup 1.0000x reference)
#include <cuda_runtime.h>
#include <cuda_bf16.h>
#include <cstdint>

#define NU 200000
#define NI 100000
#define NE 1000000
#define HD 64
#define OD 32

// ---------------- device scratch (static globals: allocation-guard safe) ----------------
__device__ float g_hu[(size_t)NU * HD];   // pre-linear users / layer-2 output (overwrite)
__device__ float g_hi[(size_t)NI * HD];
__device__ float g_x1u[(size_t)NU * HD];
__device__ float g_x1i[(size_t)NI * HD];
__device__ int   g_csr_u2i[NE];           // src user ids grouped by item dst
__device__ int   g_csr_i2u[NE];           // src item ids grouped by user dst
__device__ int   g_rsu[NU + 1];
__device__ int   g_rsi[NI + 1];
__device__ int   g_curu[NU];              // deg, then fill cursor
__device__ int   g_curi[NI];

// ---------------- zero both cursor arrays ----------------
__global__ void zero_both_kernel(int* __restrict__ curu, int* __restrict__ curi) {
    int i = blockIdx.x * blockDim.x + threadIdx.x;
    if (i < NU) curu[i] = 0;
    else if (i < NU + NI) curi[i - NU] = 0;
}

// ---------------- histogram both edge types ----------------
__global__ void hist_both_kernel(const int* __restrict__ ei_u2i, const int* __restrict__ ei_i2u,
                                 int* __restrict__ curi, int* __restrict__ curu, int eb) {
    int b = blockIdx.x;
    if (b < eb) {
        int e = b * 256 + threadIdx.x;
        if (e < NE) atomicAdd(&curi[__ldg(ei_u2i + NE + e)], 1);
    } else {
        int e = (b - eb) * 256 + threadIdx.x;
        if (e < NE) atomicAdd(&curu[__ldg(ei_i2u + NE + e)], 1);
    }
}

// ---------------- single-block exclusive scan (1024 threads, chunked) ----------------
__global__ void scan_kernel(const int* __restrict__ deg, int n, int total,
                            int* __restrict__ rs, int* __restrict__ cur) {
    __shared__ int warp_sums[32];
    __shared__ int s_carry;
    int tid = threadIdx.x, lane = tid & 31, wid = tid >> 5;
    if (tid == 0) s_carry = 0;
    __syncthreads();
    for (int base = 0; base < n; base += 1024) {
        int i = base + tid;
        int v = (i < n) ? deg[i] : 0;
        int x = v;
        #pragma unroll
        for (int d = 1; d < 32; d <<= 1) {
            int t = __shfl_up_sync(0xffffffffu, x, d);
            if (lane >= d) x += t;
        }
        if (lane == 31) warp_sums[wid] = x;
        __syncthreads();
        if (wid == 0) {
            int y = warp_sums[lane];
            #pragma unroll
            for (int d = 1; d < 32; d <<= 1) {
                int t = __shfl_up_sync(0xffffffffu, y, d);
                if (lane >= d) y += t;
            }
            warp_sums[lane] = y;
        }
        __syncthreads();
        int excl = (x - v) + (wid ? warp_sums[wid - 1] : 0) + s_carry;
        if (i < n) { rs[i] = excl; cur[i] = excl; }
        __syncthreads();
        if (tid == 0) s_carry += warp_sums[31];
        __syncthreads();
    }
    if (tid == 0) rs[n] = total;
}

// ---------------- fill both CSR arrays ----------------
__global__ void fill_both_kernel(const int* __restrict__ ei_u2i, const int* __restrict__ ei_i2u,
                                 int* __restrict__ curi, int* __restrict__ curu,
                                 int* __restrict__ csr_u2i, int* __restrict__ csr_i2u, int eb) {
    int b = blockIdx.x;
    if (b < eb) {
        int e = b * 256 + threadIdx.x;
        if (e < NE) {
            int pos = atomicAdd(&curi[__ldg(ei_u2i + NE + e)], 1);
            csr_u2i[pos] = __ldg(ei_u2i + e);
        }
    } else {
        int e = (b - eb) * 256 + threadIdx.x;
        if (e < NE) {
            int pos = atomicAdd(&curu[__ldg(ei_i2u + NE + e)], 1);
            csr_i2u[pos] = __ldg(ei_i2u + e);
        }
    }
}

// ---------------- fused linear pair: out[n,COLS] = x[n,64] @ W[COLS,64]^T + b ----------------
template <int COLS>
__global__ void __launch_bounds__(256) linear_pair_kernel(
    const float* __restrict__ x0, const float* __restrict__ W0,
    const float* __restrict__ b0, float* __restrict__ out0, int n0, int nb0,
    const float* __restrict__ x1, const float* __restrict__ W1,
    const float* __restrict__ b1, float* __restrict__ out1, int n1)
{
    const float *x, *W, *bias; float* out; int n, row0;
    if (blockIdx.x < nb0) { x = x0; W = W0; bias = b0; out = out0; n = n0; row0 = blockIdx.x * 64; }
    else { x = x1; W = W1; bias = b1; out = out1; n = n1; row0 = (blockIdx.x - nb0) * 64; }

    constexpr int WS = COLS + 4;
    __shared__ float sW[64 * WS];
    __shared__ float sX[64 * 68];
    int tid = threadIdx.x;

    for (int i = tid; i < COLS * 64; i += 256) {
        int c = i >> 6, k = i & 63;
        sW[k * WS + c] = W[i];
    }
    for (int i = tid; i < 64 * 16; i += 256) {
        int r = i >> 4, q = i & 15;
        int row = row0 + r;
        float4 v = make_float4(0.f, 0.f, 0.f, 0.f);
        if (row < n) v = __ldg((const float4*)(x + (size_t)row * 64) + q);
        *(float4*)&sX[r * 68 + q * 4] = v;
    }
    __syncthreads();

    constexpr int CPT = COLS / 4;
    int r = tid >> 2, sub = tid & 3;
    int c0 = sub * CPT;
    float o[CPT];
    #pragma unroll
    for (int i = 0; i < CPT; i++) o[i] = __ldg(bias + c0 + i);

    #pragma unroll 4
    for (int k = 0; k < 64; k++) {
        float xv = sX[r * 68 + k];
        #pragma unroll
        for (int i = 0; i < CPT / 4; i++) {
            float4 w = *(const float4*)&sW[k * WS + c0 + 4 * i];
            o[4 * i + 0] += xv * w.x;
            o[4 * i + 1] += xv * w.y;
            o[4 * i + 2] += xv * w.z;
            o[4 * i + 3] += xv * w.w;
        }
    }
    int row = row0 + r;
    if (row < n) {
        #pragma unroll
        for (int i = 0; i < CPT / 4; i++) {
            float4 v = make_float4(o[4 * i], o[4 * i + 1], o[4 * i + 2], o[4 * i + 3]);
            ((float4*)(out + (size_t)row * COLS + c0))[i] = v;
        }
    }
}

// ---- fused CSR conv, 8 threads/row (low regs -> high occupancy for gather hiding) ----
// out = relu( mean_{s in N(row)} feat[s] @ Wrel^T + brel + h[row] @ Wroot^T + h[row] )
__global__ void __launch_bounds__(256) combine8_kernel(
    const float* __restrict__ feat, const float* __restrict__ h,
    const int* __restrict__ rs, const int* __restrict__ csr,
    const float* __restrict__ Wrel, const float* __restrict__ brel,
    const float* __restrict__ Wroot,
    float* __restrict__ out, int n)
{
    __shared__ float sWrel[64 * 64];
    __shared__ float sWroot[64 * 64];
    int tid = threadIdx.x;

    for (int i = tid; i < 4096; i += 256) {
        int c = i >> 6, k = i & 63;         // W row-major [64][64] -> k-major in smem
        sWrel[k * 64 + c]  = Wrel[i];
        sWroot[k * 64 + c] = Wroot[i];
    }
    __syncthreads();

    int r = tid >> 3, sub = tid & 7;        // 32 rows/block, 8 threads/row
    int row = blockIdx.x * 32 + r;
    bool valid = row < n;
    int rr = valid ? row : 0;

    int e0 = __ldg(rs + rr), e1 = __ldg(rs + rr + 1);
    float m[8];
    #pragma unroll
    for (int i = 0; i < 8; i++) m[i] = 0.f;

    // gather: 2-edge unroll for MLP
    int e = e0;
    for (; e + 2 <= e1; e += 2) {
        int s0 = __ldg(csr + e);
        int s1 = __ldg(csr + e + 1);
        const float4* p0 = (const float4*)(feat + (size_t)s0 * 64) + sub * 2;
        const float4* p1 = (const float4*)(feat + (size_t)s1 * 64) + sub * 2;
        float4 a0 = __ldg(p0);
        float4 a1 = __ldg(p0 + 1);
        float4 b0 = __ldg(p1);
        float4 b1 = __ldg(p1 + 1);
        m[0] += a0.x + b0.x;  m[1] += a0.y + b0.y;
        m[2] += a0.z + b0.z;  m[3] += a0.w + b0.w;
        m[4] += a1.x + b1.x;  m[5] += a1.y + b1.y;
        m[6] += a1.z + b1.z;  m[7] += a1.w + b1.w;
    }
    if (e < e1) {
        int s0 = __ldg(csr + e);
        const float4* p0 = (const float4*)(feat + (size_t)s0 * 64) + sub * 2;
        float4 a0 = __ldg(p0);
        float4 a1 = __ldg(p0 + 1);
        m[0] += a0.x;  m[1] += a0.y;  m[2] += a0.z;  m[3] += a0.w;
        m[4] += a1.x;  m[5] += a1.y;  m[6] += a1.z;  m[7] += a1.w;
    }
    float id = 1.f / fmaxf((float)(e1 - e0), 1.f);
    #pragma unroll
    for (int i = 0; i < 8; i++) m[i] *= id;

    float hh[8];
    {
        const float4* hp = (const float4*)(h + (size_t)rr * 64) + sub * 2;
        float4 v0 = __ldg(hp);
        float4 v1 = __ldg(hp + 1);
        hh[0] = v0.x;  hh[1] = v0.y;  hh[2] = v0.z;  hh[3] = v0.w;
        hh[4] = v1.x;  hh[5] = v1.y;  hh[6] = v1.z;  hh[7] = v1.w;
    }

    int c0 = sub * 8;
    float o[8];
    {
        const float4* bp = (const float4*)(brel + c0);
        float4 v0 = __ldg(bp);
        float4 v1 = __ldg(bp + 1);
        o[0] = v0.x;  o[1] = v0.y;  o[2] = v0.z;  o[3] = v0.w;
        o[4] = v1.x;  o[5] = v1.y;  o[6] = v1.z;  o[7] = v1.w;
    }

    #pragma unroll
    for (int k = 0; k < 64; k++) {
        float mv = __shfl_sync(0xffffffffu, m[k & 7],  k >> 3, 8);
        float hv = __shfl_sync(0xffffffffu, hh[k & 7], k >> 3, 8);
        const float4* wrp = (const float4*)&sWrel[k * 64 + c0];
        const float4* wop = (const float4*)&sWroot[k * 64 + c0];
        float4 wr0 = wrp[0], wr1 = wrp[1];
        float4 wo0 = wop[0], wo1 = wop[1];
        o[0] += mv * wr0.x + hv * wo0.x;
        o[1] += mv * wr0.y + hv * wo0.y;
        o[2] += mv * wr0.z + hv * wo0.z;
        o[3] += mv * wr0.w + hv * wo0.w;
        o[4] += mv * wr1.x + hv * wo1.x;
        o[5] += mv * wr1.y + hv * wo1.y;
        o[6] += mv * wr1.z + hv * wo1.z;
        o[7] += mv * wr1.w + hv * wo1.w;
    }

    if (valid) {
        float4 v0, v1;
        v0.x = fmaxf(o[0] + hh[0], 0.f);
        v0.y = fmaxf(o[1] + hh[1], 0.f);
        v0.z = fmaxf(o[2] + hh[2], 0.f);
        v0.w = fmaxf(o[3] + hh[3], 0.f);
        v1.x = fmaxf(o[4] + hh[4], 0.f);
        v1.y = fmaxf(o[5] + hh[5], 0.f);
        v1.z = fmaxf(o[6] + hh[6], 0.f);
        v1.w = fmaxf(o[7] + hh[7], 0.f);
        float4* op = (float4*)(out + (size_t)row * 64 + c0);
        op[0] = v0;
        op[1] = v1;
    }
}

// ---------------- host ----------------
extern "C" void kernel_launch(void* const* d_in, const int* in_sizes, int n_in,
                              void* d_out, int out_size)
{
    const float* x_user = (const float*)d_in[0];
    const float* x_item = (const float*)d_in[1];
    const int*   ei_u2i = (const int*)d_in[2];
    const int*   ei_i2u = (const int*)d_in[3];
    const float* pre_w_u = (const float*)d_in[4];
    const float* pre_b_u = (const float*)d_in[5];
    const float* pre_w_i = (const float*)d_in[6];
    const float* pre_b_i = (const float*)d_in[7];
    const float* c1u2i_wrel  = (const float*)d_in[8];
    const float* c1u2i_brel  = (const float*)d_in[9];
    const float* c1u2i_wroot = (const float*)d_in[10];
    const float* c1i2u_wrel  = (const float*)d_in[11];
    const float* c1i2u_brel  = (const float*)d_in[12];
    const float* c1i2u_wroot = (const float*)d_in[13];
    const float* c2u2i_wrel  = (const float*)d_in[14];
    const float* c2u2i_brel  = (const float*)d_in[15];
    const float* c2u2i_wroot = (const float*)d_in[16];
    const float* c2i2u_wrel  = (const float*)d_in[17];
    const float* c2i2u_brel  = (const float*)d_in[18];
    const float* c2i2u_wroot = (const float*)d_in[19];
    const float* post_w_u = (const float*)d_in[20];
    const float* post_b_u = (const float*)d_in[21];
    const float* post_w_i = (const float*)d_in[22];
    const float* post_b_i = (const float*)d_in[23];
    float* out_u = (float*)d_out;
    float* out_i = out_u + (size_t)NU * OD;

    float *hu, *hi, *x1u, *x1i;
    int *csr_u2i, *csr_i2u, *rsu, *rsi, *curu, *curi;
    cudaGetSymbolAddress((void**)&hu,  g_hu);
    cudaGetSymbolAddress((void**)&hi,  g_hi);
    cudaGetSymbolAddress((void**)&x1u, g_x1u);
    cudaGetSymbolAddress((void**)&x1i, g_x1i);
    cudaGetSymbolAddress((void**)&csr_u2i, g_csr_u2i);
    cudaGetSymbolAddress((void**)&csr_i2u, g_csr_i2u);
    cudaGetSymbolAddress((void**)&rsu,  g_rsu);
    cudaGetSymbolAddress((void**)&rsi,  g_rsi);
    cudaGetSymbolAddress((void**)&curu, g_curu);
    cudaGetSymbolAddress((void**)&curi, g_curi);

    const int EB = (NE + 255) / 256;
    const int NUB64 = (NU + 63) / 64, NIB64 = (NI + 63) / 64;
    const int NUB32 = (NU + 31) / 32, NIB32 = (NI + 31) / 32;

    // 0: zero cursors
    zero_both_kernel<<<(NU + NI + 255) / 256, 256>>>(curu, curi);
    // 1: degree histograms (both edge types)
    hist_both_kernel<<<2 * EB, 256>>>(ei_u2i, ei_i2u, curi, curu, EB);
    // 2,3: exclusive scans
    scan_kernel<<<1, 1024>>>(curi, NI, NE, rsi, curi);
    scan_kernel<<<1, 1024>>>(curu, NU, NE, rsu, curu);
    // 4: CSR fill (both edge types)
    fill_both_kernel<<<2 * EB, 256>>>(ei_u2i, ei_i2u, curi, curu, csr_u2i, csr_i2u, EB);
    // 5: fused preprocess linears
    linear_pair_kernel<64><<<NUB64 + NIB64, 256>>>(x_user, pre_w_u, pre_b_u, hu, NU, NUB64,
                                                   x_item, pre_w_i, pre_b_i, hi, NI);
    // 6-9: fused conv layers
    combine8_kernel<<<NIB32, 256>>>(hu, hi, rsi, csr_u2i,
                                    c1u2i_wrel, c1u2i_brel, c1u2i_wroot, x1i, NI);
    combine8_kernel<<<NUB32, 256>>>(hi, hu, rsu, csr_i2u,
                                    c1i2u_wrel, c1i2u_brel, c1i2u_wroot, x1u, NU);
    combine8_kernel<<<NIB32, 256>>>(x1u, x1i, rsi, csr_u2i,
                                    c2u2i_wrel, c2u2i_brel, c2u2i_wroot, hi, NI);
    combine8_kernel<<<NUB32, 256>>>(x1i, x1u, rsu, csr_i2u,
                                    c2i2u_wrel, c2i2u_brel, c2i2u_wroot, hu, NU);
    // 10: fused postprocess linears -> output
    linear_pair_kernel<32><<<NUB64 + NIB64, 256>>>(hu, post_w_u, post_b_u, out_u, NU, NUB64,
                                                   hi, post_w_i, post_b_i, out_i, NI);
}

// round 8
// speedup vs baseline: 2.1379x; 2.1379x over previous
#include <cuda_runtime.h>
#include <cuda_bf16.h>
#include <cstdint>

#define NU 200000
#define NI 100000
#define NE 1000000
#define HD 64
#define OD 32
#define CHUNK 1024   // elements per scan chunk (256 threads * 4)

// ---------------- device scratch (static globals: allocation-guard safe) ----------------
__device__ float g_hu[(size_t)NU * HD];
__device__ float g_hi[(size_t)NI * HD];
__device__ float g_x1u[(size_t)NU * HD];
__device__ float g_x1i[(size_t)NI * HD];
__device__ int   g_csr_u2i[NE];
__device__ int   g_csr_i2u[NE];
__device__ int   g_rsu[NU + 1];
__device__ int   g_rsi[NI + 1];
__device__ int   g_curu[NU];
__device__ int   g_curi[NI];
__device__ int   g_partU[256];
__device__ int   g_partI[256];

// ---------------- zero both cursor arrays ----------------
__global__ void zero_both_kernel(int* __restrict__ curu, int* __restrict__ curi) {
    int i = blockIdx.x * blockDim.x + threadIdx.x;
    if (i < NU) curu[i] = 0;
    else if (i < NU + NI) curi[i - NU] = 0;
}

// ---------------- histogram both edge types ----------------
__global__ void hist_both_kernel(const int* __restrict__ ei_u2i, const int* __restrict__ ei_i2u,
                                 int* __restrict__ curi, int* __restrict__ curu, int eb) {
    int b = blockIdx.x;
    if (b < eb) {
        int e = b * 256 + threadIdx.x;
        if (e < NE) atomicAdd(&curi[__ldg(ei_u2i + NE + e)], 1);
    } else {
        int e = (b - eb) * 256 + threadIdx.x;
        if (e < NE) atomicAdd(&curu[__ldg(ei_i2u + NE + e)], 1);
    }
}

// ---------------- chunked scan phase 1: per-chunk sums (both types) ----------------
__global__ void chunk_both_kernel(const int* __restrict__ degI, int* __restrict__ partI, int nbi,
                                  const int* __restrict__ degU, int* __restrict__ partU) {
    __shared__ int sc[256];
    int tid = threadIdx.x;
    const int* deg; int* part; int n, b;
    if (blockIdx.x < nbi) { deg = degI; part = partI; n = NI; b = blockIdx.x; }
    else { deg = degU; part = partU; n = NU; b = blockIdx.x - nbi; }
    int base = b * CHUNK + tid * 4;
    int s = 0;
    #pragma unroll
    for (int j = 0; j < 4; j++) { int idx = base + j; if (idx < n) s += deg[idx]; }
    sc[tid] = s; __syncthreads();
    for (int d = 128; d; d >>= 1) { if (tid < d) sc[tid] += sc[tid + d]; __syncthreads(); }
    if (tid == 0) part[b] = sc[0];
}

// ---------------- chunked scan phase 2: scan partials for both (one block) ----------------
__device__ void scan_part_one(int* __restrict__ part, int nblk) {
    __shared__ int sc[256];
    int tid = threadIdx.x;
    int v = (tid < nblk) ? part[tid] : 0;
    sc[tid] = v; __syncthreads();
    for (int d = 1; d < 256; d <<= 1) {
        int t = (tid >= d) ? sc[tid - d] : 0;
        __syncthreads();
        sc[tid] += t;
        __syncthreads();
    }
    if (tid < nblk) part[tid] = sc[tid] - v;   // exclusive
    __syncthreads();
}

__global__ void scan_parts_kernel(int* __restrict__ partI, int nbi,
                                  int* __restrict__ partU, int nbu) {
    scan_part_one(partI, nbi);
    scan_part_one(partU, nbu);
}

// ---------------- chunked scan phase 3: write exclusive scan (both types) ----------------
__global__ void scanwrite_both_kernel(int* __restrict__ curi, const int* __restrict__ partI,
                                      int* __restrict__ rsi, int nbi,
                                      int* __restrict__ curu, const int* __restrict__ partU,
                                      int* __restrict__ rsu) {
    __shared__ int sc[256];
    int tid = threadIdx.x;
    int* deg; const int* part; int* rs; int n, b;
    if (blockIdx.x < nbi) { deg = curi; part = partI; rs = rsi; n = NI; b = blockIdx.x; }
    else { deg = curu; part = partU; rs = rsu; n = NU; b = blockIdx.x - nbi; }
    int base = b * CHUNK + tid * 4;
    int v[4]; int s = 0;
    #pragma unroll
    for (int j = 0; j < 4; j++) { int idx = base + j; v[j] = (idx < n) ? deg[idx] : 0; s += v[j]; }
    sc[tid] = s; __syncthreads();
    for (int d = 1; d < 256; d <<= 1) {
        int t = (tid >= d) ? sc[tid - d] : 0;
        __syncthreads();
        sc[tid] += t;
        __syncthreads();
    }
    int off = part[b] + (sc[tid] - s);
    #pragma unroll
    for (int j = 0; j < 4; j++) {
        int idx = base + j;
        if (idx < n) { rs[idx] = off; deg[idx] = off; }   // deg becomes fill cursor
        off += v[j];
    }
    if (b == 0 && tid == 0) rs[n] = NE;
}

// ---------------- fill both CSR arrays ----------------
__global__ void fill_both_kernel(const int* __restrict__ ei_u2i, const int* __restrict__ ei_i2u,
                                 int* __restrict__ curi, int* __restrict__ curu,
                                 int* __restrict__ csr_u2i, int* __restrict__ csr_i2u, int eb) {
    int b = blockIdx.x;
    if (b < eb) {
        int e = b * 256 + threadIdx.x;
        if (e < NE) {
            int pos = atomicAdd(&curi[__ldg(ei_u2i + NE + e)], 1);
            csr_u2i[pos] = __ldg(ei_u2i + e);
        }
    } else {
        int e = (b - eb) * 256 + threadIdx.x;
        if (e < NE) {
            int pos = atomicAdd(&curu[__ldg(ei_i2u + NE + e)], 1);
            csr_i2u[pos] = __ldg(ei_i2u + e);
        }
    }
}

// ---------------- fused linear pair: out[n,COLS] = x[n,64] @ W[COLS,64]^T + b ----------------
template <int COLS>
__global__ void __launch_bounds__(256) linear_pair_kernel(
    const float* __restrict__ x0, const float* __restrict__ W0,
    const float* __restrict__ b0, float* __restrict__ out0, int n0, int nb0,
    const float* __restrict__ x1, const float* __restrict__ W1,
    const float* __restrict__ b1, float* __restrict__ out1, int n1)
{
    const float *x, *W, *bias; float* out; int n, row0;
    if (blockIdx.x < nb0) { x = x0; W = W0; bias = b0; out = out0; n = n0; row0 = blockIdx.x * 64; }
    else { x = x1; W = W1; bias = b1; out = out1; n = n1; row0 = (blockIdx.x - nb0) * 64; }

    constexpr int WS = COLS + 4;
    __shared__ float sW[64 * WS];
    __shared__ float sX[64 * 68];
    int tid = threadIdx.x;

    for (int i = tid; i < COLS * 64; i += 256) {
        int c = i >> 6, k = i & 63;
        sW[k * WS + c] = W[i];
    }
    for (int i = tid; i < 64 * 16; i += 256) {
        int r = i >> 4, q = i & 15;
        int row = row0 + r;
        float4 v = make_float4(0.f, 0.f, 0.f, 0.f);
        if (row < n) v = __ldg((const float4*)(x + (size_t)row * 64) + q);
        *(float4*)&sX[r * 68 + q * 4] = v;
    }
    __syncthreads();

    constexpr int CPT = COLS / 4;
    int r = tid >> 2, sub = tid & 3;
    int c0 = sub * CPT;
    float o[CPT];
    #pragma unroll
    for (int i = 0; i < CPT; i++) o[i] = __ldg(bias + c0 + i);

    #pragma unroll 4
    for (int k = 0; k < 64; k++) {
        float xv = sX[r * 68 + k];
        #pragma unroll
        for (int i = 0; i < CPT / 4; i++) {
            float4 w = *(const float4*)&sW[k * WS + c0 + 4 * i];
            o[4 * i + 0] += xv * w.x;
            o[4 * i + 1] += xv * w.y;
            o[4 * i + 2] += xv * w.z;
            o[4 * i + 3] += xv * w.w;
        }
    }
    int row = row0 + r;
    if (row < n) {
        #pragma unroll
        for (int i = 0; i < CPT / 4; i++) {
            float4 v = make_float4(o[4 * i], o[4 * i + 1], o[4 * i + 2], o[4 * i + 3]);
            ((float4*)(out + (size_t)row * COLS + c0))[i] = v;
        }
    }
}

// ---- GEMM-tiled fused conv: out = relu( mean @ Wrel^T + brel + h @ Wroot^T + h ) ----
// 64 rows/block, 128 threads. Phase A: 2 thr/row CSR gather -> sA (mean).
// Phase B: GEMM1 (sA x Wrel), reload sW<-Wroot / sA<-h, GEMM2, epilogue.
// 4 rows x 8 cols register tile per thread -> 2.67 FMA/LDS-byte (FFMA-bound).
__global__ void __launch_bounds__(128) combine_gemm_kernel(
    const float* __restrict__ feat, const float* __restrict__ h,
    const int* __restrict__ rs, const int* __restrict__ csr,
    const float* __restrict__ Wrel, const float* __restrict__ brel,
    const float* __restrict__ Wroot,
    float* __restrict__ out, int n)
{
    __shared__ float sW[64 * 68];   // 17408 B
    __shared__ float sA[64 * 68];   // 17408 B
    int tid = threadIdx.x;
    int row0 = blockIdx.x * 64;

    // load Wrel: W row-major [c][k] -> sW[k*68+c]
    for (int i = tid; i < 4096; i += 128) {
        int c = i >> 6, k = i & 63;
        sW[k * 68 + c] = __ldg(Wrel + i);
    }

    // phase A: gather mean. 2 threads per row, 32 floats each.
    {
        int r = tid >> 1, half = tid & 1;
        int row = row0 + r;
        bool valid = row < n;
        int e0 = valid ? __ldg(rs + row) : 0;
        int e1 = valid ? __ldg(rs + row + 1) : 0;
        float acc[32];
        #pragma unroll
        for (int i = 0; i < 32; i++) acc[i] = 0.f;
        for (int e = e0; e < e1; e++) {
            int s = __ldg(csr + e);
            const float4* p = (const float4*)(feat + (size_t)s * 64) + half * 8;
            #pragma unroll
            for (int j = 0; j < 8; j++) {
                float4 v = __ldg(p + j);
                acc[4 * j + 0] += v.x;  acc[4 * j + 1] += v.y;
                acc[4 * j + 2] += v.z;  acc[4 * j + 3] += v.w;
            }
        }
        float id = 1.f / fmaxf((float)(e1 - e0), 1.f);
        float* dst = &sA[r * 68 + half * 32];
        #pragma unroll
        for (int j = 0; j < 8; j++) {
            float4 v = make_float4(acc[4 * j] * id, acc[4 * j + 1] * id,
                                   acc[4 * j + 2] * id, acc[4 * j + 3] * id);
            *(float4*)(dst + 4 * j) = v;
        }
    }
    __syncthreads();

    // register tile: rows ro..ro+3, cols c0..c0+7
    int rg = tid >> 3, cg = tid & 7;
    int ro = rg * 4, c0 = cg * 8;
    float o[32];
    {
        float4 b0 = __ldg((const float4*)(brel + c0));
        float4 b1 = __ldg((const float4*)(brel + c0) + 1);
        #pragma unroll
        for (int i = 0; i < 4; i++) {
            o[8 * i + 0] = b0.x;  o[8 * i + 1] = b0.y;
            o[8 * i + 2] = b0.z;  o[8 * i + 3] = b0.w;
            o[8 * i + 4] = b1.x;  o[8 * i + 5] = b1.y;
            o[8 * i + 6] = b1.z;  o[8 * i + 7] = b1.w;
        }
    }

    // GEMM1: o += mean @ Wrel^T
    #pragma unroll 4
    for (int k = 0; k < 64; k++) {
        float4 w0 = *(const float4*)&sW[k * 68 + c0];
        float4 w1 = *(const float4*)&sW[k * 68 + c0 + 4];
        #pragma unroll
        for (int i = 0; i < 4; i++) {
            float a = sA[(ro + i) * 68 + k];
            o[8 * i + 0] += a * w0.x;  o[8 * i + 1] += a * w0.y;
            o[8 * i + 2] += a * w0.z;  o[8 * i + 3] += a * w0.w;
            o[8 * i + 4] += a * w1.x;  o[8 * i + 5] += a * w1.y;
            o[8 * i + 6] += a * w1.z;  o[8 * i + 7] += a * w1.w;
        }
    }
    __syncthreads();

    // reload: sW <- Wroot, sA <- h
    for (int i = tid; i < 4096; i += 128) {
        int c = i >> 6, k = i & 63;
        sW[k * 68 + c] = __ldg(Wroot + i);
    }
    {
        int r = tid >> 1, half = tid & 1;
        int row = row0 + r;
        bool valid = row < n;
        int rr = valid ? row : 0;
        const float4* hp = (const float4*)(h + (size_t)rr * 64) + half * 8;
        float* dst = &sA[r * 68 + half * 32];
        #pragma unroll
        for (int j = 0; j < 8; j++) {
            float4 v = valid ? __ldg(hp + j) : make_float4(0.f, 0.f, 0.f, 0.f);
            *(float4*)(dst + 4 * j) = v;
        }
    }
    __syncthreads();

    // GEMM2: o += h @ Wroot^T
    #pragma unroll 4
    for (int k = 0; k < 64; k++) {
        float4 w0 = *(const float4*)&sW[k * 68 + c0];
        float4 w1 = *(const float4*)&sW[k * 68 + c0 + 4];
        #pragma unroll
        for (int i = 0; i < 4; i++) {
            float a = sA[(ro + i) * 68 + k];
            o[8 * i + 0] += a * w0.x;  o[8 * i + 1] += a * w0.y;
            o[8 * i + 2] += a * w0.z;  o[8 * i + 3] += a * w0.w;
            o[8 * i + 4] += a * w1.x;  o[8 * i + 5] += a * w1.y;
            o[8 * i + 6] += a * w1.z;  o[8 * i + 7] += a * w1.w;
        }
    }

    // epilogue: + skip(h) -> relu -> store
    #pragma unroll
    for (int i = 0; i < 4; i++) {
        int row = row0 + ro + i;
        if (row < n) {
            float4 s0 = *(const float4*)&sA[(ro + i) * 68 + c0];
            float4 s1 = *(const float4*)&sA[(ro + i) * 68 + c0 + 4];
            float4 v0, v1;
            v0.x = fmaxf(o[8 * i + 0] + s0.x, 0.f);
            v0.y = fmaxf(o[8 * i + 1] + s0.y, 0.f);
            v0.z = fmaxf(o[8 * i + 2] + s0.z, 0.f);
            v0.w = fmaxf(o[8 * i + 3] + s0.w, 0.f);
            v1.x = fmaxf(o[8 * i + 4] + s1.x, 0.f);
            v1.y = fmaxf(o[8 * i + 5] + s1.y, 0.f);
            v1.z = fmaxf(o[8 * i + 6] + s1.z, 0.f);
            v1.w = fmaxf(o[8 * i + 7] + s1.w, 0.f);
            float4* op = (float4*)(out + (size_t)row * 64 + c0);
            op[0] = v0;
            op[1] = v1;
        }
    }
}

// ---------------- host ----------------
extern "C" void kernel_launch(void* const* d_in, const int* in_sizes, int n_in,
                              void* d_out, int out_size)
{
    const float* x_user = (const float*)d_in[0];
    const float* x_item = (const float*)d_in[1];
    const int*   ei_u2i = (const int*)d_in[2];
    const int*   ei_i2u = (const int*)d_in[3];
    const float* pre_w_u = (const float*)d_in[4];
    const float* pre_b_u = (const float*)d_in[5];
    const float* pre_w_i = (const float*)d_in[6];
    const float* pre_b_i = (const float*)d_in[7];
    const float* c1u2i_wrel  = (const float*)d_in[8];
    const float* c1u2i_brel  = (const float*)d_in[9];
    const float* c1u2i_wroot = (const float*)d_in[10];
    const float* c1i2u_wrel  = (const float*)d_in[11];
    const float* c1i2u_brel  = (const float*)d_in[12];
    const float* c1i2u_wroot = (const float*)d_in[13];
    const float* c2u2i_wrel  = (const float*)d_in[14];
    const float* c2u2i_brel  = (const float*)d_in[15];
    const float* c2u2i_wroot = (const float*)d_in[16];
    const float* c2i2u_wrel  = (const float*)d_in[17];
    const float* c2i2u_brel  = (const float*)d_in[18];
    const float* c2i2u_wroot = (const float*)d_in[19];
    const float* post_w_u = (const float*)d_in[20];
    const float* post_b_u = (const float*)d_in[21];
    const float* post_w_i = (const float*)d_in[22];
    const float* post_b_i = (const float*)d_in[23];
    float* out_u = (float*)d_out;
    float* out_i = out_u + (size_t)NU * OD;

    float *hu, *hi, *x1u, *x1i;
    int *csr_u2i, *csr_i2u, *rsu, *rsi, *curu, *curi, *partU, *partI;
    cudaGetSymbolAddress((void**)&hu,  g_hu);
    cudaGetSymbolAddress((void**)&hi,  g_hi);
    cudaGetSymbolAddress((void**)&x1u, g_x1u);
    cudaGetSymbolAddress((void**)&x1i, g_x1i);
    cudaGetSymbolAddress((void**)&csr_u2i, g_csr_u2i);
    cudaGetSymbolAddress((void**)&csr_i2u, g_csr_i2u);
    cudaGetSymbolAddress((void**)&rsu,  g_rsu);
    cudaGetSymbolAddress((void**)&rsi,  g_rsi);
    cudaGetSymbolAddress((void**)&curu, g_curu);
    cudaGetSymbolAddress((void**)&curi, g_curi);
    cudaGetSymbolAddress((void**)&partU, g_partU);
    cudaGetSymbolAddress((void**)&partI, g_partI);

    const int EB = (NE + 255) / 256;
    const int NUB64 = (NU + 63) / 64, NIB64 = (NI + 63) / 64;
    const int NBLKI = (NI + CHUNK - 1) / CHUNK;   // 98
    const int NBLKU = (NU + CHUNK - 1) / CHUNK;   // 196

    // CSR build (6 launches)
    zero_both_kernel<<<(NU + NI + 255) / 256, 256>>>(curu, curi);
    hist_both_kernel<<<2 * EB, 256>>>(ei_u2i, ei_i2u, curi, curu, EB);
    chunk_both_kernel<<<NBLKI + NBLKU, 256>>>(curi, partI, NBLKI, curu, partU);
    scan_parts_kernel<<<1, 256>>>(partI, NBLKI, partU, NBLKU);
    scanwrite_both_kernel<<<NBLKI + NBLKU, 256>>>(curi, partI, rsi, NBLKI, curu, partU, rsu);
    fill_both_kernel<<<2 * EB, 256>>>(ei_u2i, ei_i2u, curi, curu, csr_u2i, csr_i2u, EB);

    // preprocess linears
    linear_pair_kernel<64><<<NUB64 + NIB64, 256>>>(x_user, pre_w_u, pre_b_u, hu, NU, NUB64,
                                                   x_item, pre_w_i, pre_b_i, hi, NI);
    // layer 1
    combine_gemm_kernel<<<NIB64, 128>>>(hu, hi, rsi, csr_u2i,
                                        c1u2i_wrel, c1u2i_brel, c1u2i_wroot, x1i, NI);
    combine_gemm_kernel<<<NUB64, 128>>>(hi, hu, rsu, csr_i2u,
                                        c1i2u_wrel, c1i2u_brel, c1i2u_wroot, x1u, NU);
    // layer 2 (outputs overwrite pre-linear buffers)
    combine_gemm_kernel<<<NIB64, 128>>>(x1u, x1i, rsi, csr_u2i,
                                        c2u2i_wrel, c2u2i_brel, c2u2i_wroot, hi, NI);
    combine_gemm_kernel<<<NUB64, 128>>>(x1i, x1u, rsu, csr_i2u,
                                        c2i2u_wrel, c2i2u_brel, c2i2u_wroot, hu, NU);
    // postprocess linears -> output
    linear_pair_kernel<32><<<NUB64 + NIB64, 256>>>(hu, post_w_u, post_b_u, out_u, NU, NUB64,
                                                   hi, post_w_i, post_b_i, out_i, NI);
}

// round 9
// speedup vs baseline: 2.1388x; 1.0004x over previous
#include <cuda_runtime.h>
#include <cuda_bf16.h>
#include <cstdint>

#define NU 200000
#define NI 100000
#define NE 1000000
#define HD 64
#define OD 32
#define CHUNK 1024   // elements per scan chunk (256 threads * 4)

// ---------------- device scratch (static globals: allocation-guard safe) ----------------
__device__ float g_hu[(size_t)NU * HD];
__device__ float g_hi[(size_t)NI * HD];
__device__ float g_x1u[(size_t)NU * HD];
__device__ float g_x1i[(size_t)NI * HD];
__device__ int   g_csr_u2i[NE];
__device__ int   g_csr_i2u[NE];
__device__ int   g_rsu[NU + 1];
__device__ int   g_rsi[NI + 1];
__device__ int   g_curu[NU];
__device__ int   g_curi[NI];
__device__ int   g_partU[256];
__device__ int   g_partI[256];

// ---------------- zero both cursor arrays ----------------
__global__ void zero_both_kernel(int* __restrict__ curu, int* __restrict__ curi) {
    int i = blockIdx.x * blockDim.x + threadIdx.x;
    if (i < NU) curu[i] = 0;
    else if (i < NU + NI) curi[i - NU] = 0;
}

// ---------------- histogram both edge types ----------------
__global__ void hist_both_kernel(const int* __restrict__ ei_u2i, const int* __restrict__ ei_i2u,
                                 int* __restrict__ curi, int* __restrict__ curu, int eb) {
    int b = blockIdx.x;
    if (b < eb) {
        int e = b * 256 + threadIdx.x;
        if (e < NE) atomicAdd(&curi[__ldg(ei_u2i + NE + e)], 1);
    } else {
        int e = (b - eb) * 256 + threadIdx.x;
        if (e < NE) atomicAdd(&curu[__ldg(ei_i2u + NE + e)], 1);
    }
}

// ---------------- chunked scan phase 1: per-chunk sums (both types) ----------------
__global__ void chunk_both_kernel(const int* __restrict__ degI, int* __restrict__ partI, int nbi,
                                  const int* __restrict__ degU, int* __restrict__ partU) {
    __shared__ int sc[256];
    int tid = threadIdx.x;
    const int* deg; int* part; int n, b;
    if (blockIdx.x < nbi) { deg = degI; part = partI; n = NI; b = blockIdx.x; }
    else { deg = degU; part = partU; n = NU; b = blockIdx.x - nbi; }
    int base = b * CHUNK + tid * 4;
    int s = 0;
    #pragma unroll
    for (int j = 0; j < 4; j++) { int idx = base + j; if (idx < n) s += deg[idx]; }
    sc[tid] = s; __syncthreads();
    for (int d = 128; d; d >>= 1) { if (tid < d) sc[tid] += sc[tid + d]; __syncthreads(); }
    if (tid == 0) part[b] = sc[0];
}

// ---------------- chunked scan phase 2: scan partials for both (one block) ----------------
__device__ void scan_part_one(int* __restrict__ part, int nblk) {
    __shared__ int sc[256];
    int tid = threadIdx.x;
    int v = (tid < nblk) ? part[tid] : 0;
    sc[tid] = v; __syncthreads();
    for (int d = 1; d < 256; d <<= 1) {
        int t = (tid >= d) ? sc[tid - d] : 0;
        __syncthreads();
        sc[tid] += t;
        __syncthreads();
    }
    if (tid < nblk) part[tid] = sc[tid] - v;   // exclusive
    __syncthreads();
}

__global__ void scan_parts_kernel(int* __restrict__ partI, int nbi,
                                  int* __restrict__ partU, int nbu) {
    scan_part_one(partI, nbi);
    scan_part_one(partU, nbu);
}

// ---------------- chunked scan phase 3: write exclusive scan (both types) ----------------
__global__ void scanwrite_both_kernel(int* __restrict__ curi, const int* __restrict__ partI,
                                      int* __restrict__ rsi, int nbi,
                                      int* __restrict__ curu, const int* __restrict__ partU,
                                      int* __restrict__ rsu) {
    __shared__ int sc[256];
    int tid = threadIdx.x;
    int* deg; const int* part; int* rs; int n, b;
    if (blockIdx.x < nbi) { deg = curi; part = partI; rs = rsi; n = NI; b = blockIdx.x; }
    else { deg = curu; part = partU; rs = rsu; n = NU; b = blockIdx.x - nbi; }
    int base = b * CHUNK + tid * 4;
    int v[4]; int s = 0;
    #pragma unroll
    for (int j = 0; j < 4; j++) { int idx = base + j; v[j] = (idx < n) ? deg[idx] : 0; s += v[j]; }
    sc[tid] = s; __syncthreads();
    for (int d = 1; d < 256; d <<= 1) {
        int t = (tid >= d) ? sc[tid - d] : 0;
        __syncthreads();
        sc[tid] += t;
        __syncthreads();
    }
    int off = part[b] + (sc[tid] - s);
    #pragma unroll
    for (int j = 0; j < 4; j++) {
        int idx = base + j;
        if (idx < n) { rs[idx] = off; deg[idx] = off; }   // deg becomes fill cursor
        off += v[j];
    }
    if (b == 0 && tid == 0) rs[n] = NE;
}

// ---------------- fill both CSR arrays ----------------
__global__ void fill_both_kernel(const int* __restrict__ ei_u2i, const int* __restrict__ ei_i2u,
                                 int* __restrict__ curi, int* __restrict__ curu,
                                 int* __restrict__ csr_u2i, int* __restrict__ csr_i2u, int eb) {
    int b = blockIdx.x;
    if (b < eb) {
        int e = b * 256 + threadIdx.x;
        if (e < NE) {
            int pos = atomicAdd(&curi[__ldg(ei_u2i + NE + e)], 1);
            csr_u2i[pos] = __ldg(ei_u2i + e);
        }
    } else {
        int e = (b - eb) * 256 + threadIdx.x;
        if (e < NE) {
            int pos = atomicAdd(&curu[__ldg(ei_i2u + NE + e)], 1);
            csr_i2u[pos] = __ldg(ei_i2u + e);
        }
    }
}

// ---------------- fused linear pair: out[n,COLS] = x[n,64] @ W[COLS,64]^T + b ----------------
template <int COLS>
__global__ void __launch_bounds__(256) linear_pair_kernel(
    const float* __restrict__ x0, const float* __restrict__ W0,
    const float* __restrict__ b0, float* __restrict__ out0, int n0, int nb0,
    const float* __restrict__ x1, const float* __restrict__ W1,
    const float* __restrict__ b1, float* __restrict__ out1, int n1)
{
    const float *x, *W, *bias; float* out; int n, row0;
    if (blockIdx.x < nb0) { x = x0; W = W0; bias = b0; out = out0; n = n0; row0 = blockIdx.x * 64; }
    else { x = x1; W = W1; bias = b1; out = out1; n = n1; row0 = (blockIdx.x - nb0) * 64; }

    constexpr int WS = COLS + 4;
    __shared__ float sW[64 * WS];
    __shared__ float sX[64 * 68];
    int tid = threadIdx.x;

    for (int i = tid; i < COLS * 64; i += 256) {
        int c = i >> 6, k = i & 63;
        sW[k * WS + c] = W[i];
    }
    for (int i = tid; i < 64 * 16; i += 256) {
        int r = i >> 4, q = i & 15;
        int row = row0 + r;
        float4 v = make_float4(0.f, 0.f, 0.f, 0.f);
        if (row < n) v = __ldg((const float4*)(x + (size_t)row * 64) + q);
        *(float4*)&sX[r * 68 + q * 4] = v;
    }
    __syncthreads();

    constexpr int CPT = COLS / 4;
    int r = tid >> 2, sub = tid & 3;
    int c0 = sub * CPT;
    float o[CPT];
    #pragma unroll
    for (int i = 0; i < CPT; i++) o[i] = __ldg(bias + c0 + i);

    #pragma unroll 4
    for (int k = 0; k < 64; k++) {
        float xv = sX[r * 68 + k];
        #pragma unroll
        for (int i = 0; i < CPT / 4; i++) {
            float4 w = *(const float4*)&sW[k * WS + c0 + 4 * i];
            o[4 * i + 0] += xv * w.x;
            o[4 * i + 1] += xv * w.y;
            o[4 * i + 2] += xv * w.z;
            o[4 * i + 3] += xv * w.w;
        }
    }
    int row = row0 + r;
    if (row < n) {
        #pragma unroll
        for (int i = 0; i < CPT / 4; i++) {
            float4 v = make_float4(o[4 * i], o[4 * i + 1], o[4 * i + 2], o[4 * i + 3]);
            ((float4*)(out + (size_t)row * COLS + c0))[i] = v;
        }
    }
}

// ---- GEMM-tiled fused conv: out = relu( mean @ Wrel^T + brel + h @ Wroot^T + h ) ----
// 64 rows/block, 128 threads. Phase A: 2 thr/row CSR gather -> sA (mean).
// Phase B: GEMM1 (sA x Wrel), reload sW<-Wroot / sA<-h, GEMM2, epilogue.
// 4 rows x 8 cols register tile per thread -> 2.67 FMA/LDS-byte (FFMA-bound).
__global__ void __launch_bounds__(128) combine_gemm_kernel(
    const float* __restrict__ feat, const float* __restrict__ h,
    const int* __restrict__ rs, const int* __restrict__ csr,
    const float* __restrict__ Wrel, const float* __restrict__ brel,
    const float* __restrict__ Wroot,
    float* __restrict__ out, int n)
{
    __shared__ float sW[64 * 68];   // 17408 B
    __shared__ float sA[64 * 68];   // 17408 B
    int tid = threadIdx.x;
    int row0 = blockIdx.x * 64;

    // load Wrel: W row-major [c][k] -> sW[k*68+c]
    for (int i = tid; i < 4096; i += 128) {
        int c = i >> 6, k = i & 63;
        sW[k * 68 + c] = __ldg(Wrel + i);
    }

    // phase A: gather mean. 2 threads per row, 32 floats each.
    {
        int r = tid >> 1, half = tid & 1;
        int row = row0 + r;
        bool valid = row < n;
        int e0 = valid ? __ldg(rs + row) : 0;
        int e1 = valid ? __ldg(rs + row + 1) : 0;
        float acc[32];
        #pragma unroll
        for (int i = 0; i < 32; i++) acc[i] = 0.f;
        for (int e = e0; e < e1; e++) {
            int s = __ldg(csr + e);
            const float4* p = (const float4*)(feat + (size_t)s * 64) + half * 8;
            #pragma unroll
            for (int j = 0; j < 8; j++) {
                float4 v = __ldg(p + j);
                acc[4 * j + 0] += v.x;  acc[4 * j + 1] += v.y;
                acc[4 * j + 2] += v.z;  acc[4 * j + 3] += v.w;
            }
        }
        float id = 1.f / fmaxf((float)(e1 - e0), 1.f);
        float* dst = &sA[r * 68 + half * 32];
        #pragma unroll
        for (int j = 0; j < 8; j++) {
            float4 v = make_float4(acc[4 * j] * id, acc[4 * j + 1] * id,
                                   acc[4 * j + 2] * id, acc[4 * j + 3] * id);
            *(float4*)(dst + 4 * j) = v;
        }
    }
    __syncthreads();

    // register tile: rows ro..ro+3, cols c0..c0+7
    int rg = tid >> 3, cg = tid & 7;
    int ro = rg * 4, c0 = cg * 8;
    float o[32];
    {
        float4 b0 = __ldg((const float4*)(brel + c0));
        float4 b1 = __ldg((const float4*)(brel + c0) + 1);
        #pragma unroll
        for (int i = 0; i < 4; i++) {
            o[8 * i + 0] = b0.x;  o[8 * i + 1] = b0.y;
            o[8 * i + 2] = b0.z;  o[8 * i + 3] = b0.w;
            o[8 * i + 4] = b1.x;  o[8 * i + 5] = b1.y;
            o[8 * i + 6] = b1.z;  o[8 * i + 7] = b1.w;
        }
    }

    // GEMM1: o += mean @ Wrel^T
    #pragma unroll 4
    for (int k = 0; k < 64; k++) {
        float4 w0 = *(const float4*)&sW[k * 68 + c0];
        float4 w1 = *(const float4*)&sW[k * 68 + c0 + 4];
        #pragma unroll
        for (int i = 0; i < 4; i++) {
            float a = sA[(ro + i) * 68 + k];
            o[8 * i + 0] += a * w0.x;  o[8 * i + 1] += a * w0.y;
            o[8 * i + 2] += a * w0.z;  o[8 * i + 3] += a * w0.w;
            o[8 * i + 4] += a * w1.x;  o[8 * i + 5] += a * w1.y;
            o[8 * i + 6] += a * w1.z;  o[8 * i + 7] += a * w1.w;
        }
    }
    __syncthreads();

    // reload: sW <- Wroot, sA <- h
    for (int i = tid; i < 4096; i += 128) {
        int c = i >> 6, k = i & 63;
        sW[k * 68 + c] = __ldg(Wroot + i);
    }
    {
        int r = tid >> 1, half = tid & 1;
        int row = row0 + r;
        bool valid = row < n;
        int rr = valid ? row : 0;
        const float4* hp = (const float4*)(h + (size_t)rr * 64) + half * 8;
        float* dst = &sA[r * 68 + half * 32];
        #pragma unroll
        for (int j = 0; j < 8; j++) {
            float4 v = valid ? __ldg(hp + j) : make_float4(0.f, 0.f, 0.f, 0.f);
            *(float4*)(dst + 4 * j) = v;
        }
    }
    __syncthreads();

    // GEMM2: o += h @ Wroot^T
    #pragma unroll 4
    for (int k = 0; k < 64; k++) {
        float4 w0 = *(const float4*)&sW[k * 68 + c0];
        float4 w1 = *(const float4*)&sW[k * 68 + c0 + 4];
        #pragma unroll
        for (int i = 0; i < 4; i++) {
            float a = sA[(ro + i) * 68 + k];
            o[8 * i + 0] += a * w0.x;  o[8 * i + 1] += a * w0.y;
            o[8 * i + 2] += a * w0.z;  o[8 * i + 3] += a * w0.w;
            o[8 * i + 4] += a * w1.x;  o[8 * i + 5] += a * w1.y;
            o[8 * i + 6] += a * w1.z;  o[8 * i + 7] += a * w1.w;
        }
    }

    // epilogue: + skip(h) -> relu -> store
    #pragma unroll
    for (int i = 0; i < 4; i++) {
        int row = row0 + ro + i;
        if (row < n) {
            float4 s0 = *(const float4*)&sA[(ro + i) * 68 + c0];
            float4 s1 = *(const float4*)&sA[(ro + i) * 68 + c0 + 4];
            float4 v0, v1;
            v0.x = fmaxf(o[8 * i + 0] + s0.x, 0.f);
            v0.y = fmaxf(o[8 * i + 1] + s0.y, 0.f);
            v0.z = fmaxf(o[8 * i + 2] + s0.z, 0.f);
            v0.w = fmaxf(o[8 * i + 3] + s0.w, 0.f);
            v1.x = fmaxf(o[8 * i + 4] + s1.x, 0.f);
            v1.y = fmaxf(o[8 * i + 5] + s1.y, 0.f);
            v1.z = fmaxf(o[8 * i + 6] + s1.z, 0.f);
            v1.w = fmaxf(o[8 * i + 7] + s1.w, 0.f);
            float4* op = (float4*)(out + (size_t)row * 64 + c0);
            op[0] = v0;
            op[1] = v1;
        }
    }
}

// ---------------- host ----------------
extern "C" void kernel_launch(void* const* d_in, const int* in_sizes, int n_in,
                              void* d_out, int out_size)
{
    const float* x_user = (const float*)d_in[0];
    const float* x_item = (const float*)d_in[1];
    const int*   ei_u2i = (const int*)d_in[2];
    const int*   ei_i2u = (const int*)d_in[3];
    const float* pre_w_u = (const float*)d_in[4];
    const float* pre_b_u = (const float*)d_in[5];
    const float* pre_w_i = (const float*)d_in[6];
    const float* pre_b_i = (const float*)d_in[7];
    const float* c1u2i_wrel  = (const float*)d_in[8];
    const float* c1u2i_brel  = (const float*)d_in[9];
    const float* c1u2i_wroot = (const float*)d_in[10];
    const float* c1i2u_wrel  = (const float*)d_in[11];
    const float* c1i2u_brel  = (const float*)d_in[12];
    const float* c1i2u_wroot = (const float*)d_in[13];
    const float* c2u2i_wrel  = (const float*)d_in[14];
    const float* c2u2i_brel  = (const float*)d_in[15];
    const float* c2u2i_wroot = (const float*)d_in[16];
    const float* c2i2u_wrel  = (const float*)d_in[17];
    const float* c2i2u_brel  = (const float*)d_in[18];
    const float* c2i2u_wroot = (const float*)d_in[19];
    const float* post_w_u = (const float*)d_in[20];
    const float* post_b_u = (const float*)d_in[21];
    const float* post_w_i = (const float*)d_in[22];
    const float* post_b_i = (const float*)d_in[23];
    float* out_u = (float*)d_out;
    float* out_i = out_u + (size_t)NU * OD;

    float *hu, *hi, *x1u, *x1i;
    int *csr_u2i, *csr_i2u, *rsu, *rsi, *curu, *curi, *partU, *partI;
    cudaGetSymbolAddress((void**)&hu,  g_hu);
    cudaGetSymbolAddress((void**)&hi,  g_hi);
    cudaGetSymbolAddress((void**)&x1u, g_x1u);
    cudaGetSymbolAddress((void**)&x1i, g_x1i);
    cudaGetSymbolAddress((void**)&csr_u2i, g_csr_u2i);
    cudaGetSymbolAddress((void**)&csr_i2u, g_csr_i2u);
    cudaGetSymbolAddress((void**)&rsu,  g_rsu);
    cudaGetSymbolAddress((void**)&rsi,  g_rsi);
    cudaGetSymbolAddress((void**)&curu, g_curu);
    cudaGetSymbolAddress((void**)&curi, g_curi);
    cudaGetSymbolAddress((void**)&partU, g_partU);
    cudaGetSymbolAddress((void**)&partI, g_partI);

    const int EB = (NE + 255) / 256;
    const int NUB64 = (NU + 63) / 64, NIB64 = (NI + 63) / 64;
    const int NBLKI = (NI + CHUNK - 1) / CHUNK;   // 98
    const int NBLKU = (NU + CHUNK - 1) / CHUNK;   // 196

    // CSR build (6 launches)
    zero_both_kernel<<<(NU + NI + 255) / 256, 256>>>(curu, curi);
    hist_both_kernel<<<2 * EB, 256>>>(ei_u2i, ei_i2u, curi, curu, EB);
    chunk_both_kernel<<<NBLKI + NBLKU, 256>>>(curi, partI, NBLKI, curu, partU);
    scan_parts_kernel<<<1, 256>>>(partI, NBLKI, partU, NBLKU);
    scanwrite_both_kernel<<<NBLKI + NBLKU, 256>>>(curi, partI, rsi, NBLKI, curu, partU, rsu);
    fill_both_kernel<<<2 * EB, 256>>>(ei_u2i, ei_i2u, curi, curu, csr_u2i, csr_i2u, EB);

    // preprocess linears
    linear_pair_kernel<64><<<NUB64 + NIB64, 256>>>(x_user, pre_w_u, pre_b_u, hu, NU, NUB64,
                                                   x_item, pre_w_i, pre_b_i, hi, NI);
    // layer 1
    combine_gemm_kernel<<<NIB64, 128>>>(hu, hi, rsi, csr_u2i,
                                        c1u2i_wrel, c1u2i_brel, c1u2i_wroot, x1i, NI);
    combine_gemm_kernel<<<NUB64, 128>>>(hi, hu, rsu, csr_i2u,
                                        c1i2u_wrel, c1i2u_brel, c1i2u_wroot, x1u, NU);
    // layer 2 (outputs overwrite pre-linear buffers)
    combine_gemm_kernel<<<NIB64, 128>>>(x1u, x1i, rsi, csr_u2i,
                                        c2u2i_wrel, c2u2i_brel, c2u2i_wroot, hi, NI);
    combine_gemm_kernel<<<NUB64, 128>>>(x1i, x1u, rsu, csr_i2u,
                                        c2i2u_wrel, c2i2u_brel, c2i2u_wroot, hu, NU);
    // postprocess linears -> output
    linear_pair_kernel<32><<<NUB64 + NIB64, 256>>>(hu, post_w_u, post_b_u, out_u, NU, NUB64,
                                                   hi, post_w_i, post_b_i, out_i, NI);
}

// round 10
// speedup vs baseline: 2.1452x; 1.0030x over previous
#include <cuda_runtime.h>
#include <cuda_bf16.h>
#include <cstdint>

#define NU 200000
#define NI 100000
#define NE 1000000
#define HD 64
#define OD 32
#define CHUNK 1024   // elements per scan chunk (256 threads * 4)

// ---------------- device scratch (static globals: allocation-guard safe) ----------------
__device__ float g_hu[(size_t)NU * HD];
__device__ float g_hi[(size_t)NI * HD];
__device__ float g_x1u[(size_t)NU * HD];
__device__ float g_x1i[(size_t)NI * HD];
__device__ int   g_csr_u2i[NE];
__device__ int   g_csr_i2u[NE];
__device__ int   g_rsu[NU + 1];
__device__ int   g_rsi[NI + 1];
__device__ int   g_curu[NU];
__device__ int   g_curi[NI];
__device__ int   g_partU[256];
__device__ int   g_partI[256];

// ---------------- zero both cursor arrays ----------------
__global__ void zero_both_kernel(int* __restrict__ curu, int* __restrict__ curi) {
    int i = blockIdx.x * blockDim.x + threadIdx.x;
    if (i < NU) curu[i] = 0;
    else if (i < NU + NI) curi[i - NU] = 0;
}

// ---------------- histogram both edge types ----------------
__global__ void hist_both_kernel(const int* __restrict__ ei_u2i, const int* __restrict__ ei_i2u,
                                 int* __restrict__ curi, int* __restrict__ curu, int eb) {
    int b = blockIdx.x;
    if (b < eb) {
        int e = b * 256 + threadIdx.x;
        if (e < NE) atomicAdd(&curi[__ldg(ei_u2i + NE + e)], 1);
    } else {
        int e = (b - eb) * 256 + threadIdx.x;
        if (e < NE) atomicAdd(&curu[__ldg(ei_i2u + NE + e)], 1);
    }
}

// ---------------- chunked scan phase 1: per-chunk sums (both types) ----------------
__global__ void chunk_both_kernel(const int* __restrict__ degI, int* __restrict__ partI, int nbi,
                                  const int* __restrict__ degU, int* __restrict__ partU) {
    __shared__ int sc[256];
    int tid = threadIdx.x;
    const int* deg; int* part; int n, b;
    if (blockIdx.x < nbi) { deg = degI; part = partI; n = NI; b = blockIdx.x; }
    else { deg = degU; part = partU; n = NU; b = blockIdx.x - nbi; }
    int base = b * CHUNK + tid * 4;
    int s = 0;
    #pragma unroll
    for (int j = 0; j < 4; j++) { int idx = base + j; if (idx < n) s += deg[idx]; }
    sc[tid] = s; __syncthreads();
    for (int d = 128; d; d >>= 1) { if (tid < d) sc[tid] += sc[tid + d]; __syncthreads(); }
    if (tid == 0) part[b] = sc[0];
}

// ---------------- chunked scan phase 2: scan partials for both (one block) ----------------
__device__ void scan_part_one(int* __restrict__ part, int nblk) {
    __shared__ int sc[256];
    int tid = threadIdx.x;
    int v = (tid < nblk) ? part[tid] : 0;
    sc[tid] = v; __syncthreads();
    for (int d = 1; d < 256; d <<= 1) {
        int t = (tid >= d) ? sc[tid - d] : 0;
        __syncthreads();
        sc[tid] += t;
        __syncthreads();
    }
    if (tid < nblk) part[tid] = sc[tid] - v;   // exclusive
    __syncthreads();
}

__global__ void scan_parts_kernel(int* __restrict__ partI, int nbi,
                                  int* __restrict__ partU, int nbu) {
    scan_part_one(partI, nbi);
    scan_part_one(partU, nbu);
}

// ---------------- chunked scan phase 3: write exclusive scan (both types) ----------------
__global__ void scanwrite_both_kernel(int* __restrict__ curi, const int* __restrict__ partI,
                                      int* __restrict__ rsi, int nbi,
                                      int* __restrict__ curu, const int* __restrict__ partU,
                                      int* __restrict__ rsu) {
    __shared__ int sc[256];
    int tid = threadIdx.x;
    int* deg; const int* part; int* rs; int n, b;
    if (blockIdx.x < nbi) { deg = curi; part = partI; rs = rsi; n = NI; b = blockIdx.x; }
    else { deg = curu; part = partU; rs = rsu; n = NU; b = blockIdx.x - nbi; }
    int base = b * CHUNK + tid * 4;
    int v[4]; int s = 0;
    #pragma unroll
    for (int j = 0; j < 4; j++) { int idx = base + j; v[j] = (idx < n) ? deg[idx] : 0; s += v[j]; }
    sc[tid] = s; __syncthreads();
    for (int d = 1; d < 256; d <<= 1) {
        int t = (tid >= d) ? sc[tid - d] : 0;
        __syncthreads();
        sc[tid] += t;
        __syncthreads();
    }
    int off = part[b] + (sc[tid] - s);
    #pragma unroll
    for (int j = 0; j < 4; j++) {
        int idx = base + j;
        if (idx < n) { rs[idx] = off; deg[idx] = off; }   // deg becomes fill cursor
        off += v[j];
    }
    if (b == 0 && tid == 0) rs[n] = NE;
}

// ---------------- fill both CSR arrays ----------------
__global__ void fill_both_kernel(const int* __restrict__ ei_u2i, const int* __restrict__ ei_i2u,
                                 int* __restrict__ curi, int* __restrict__ curu,
                                 int* __restrict__ csr_u2i, int* __restrict__ csr_i2u, int eb) {
    int b = blockIdx.x;
    if (b < eb) {
        int e = b * 256 + threadIdx.x;
        if (e < NE) {
            int pos = atomicAdd(&curi[__ldg(ei_u2i + NE + e)], 1);
            csr_u2i[pos] = __ldg(ei_u2i + e);
        }
    } else {
        int e = (b - eb) * 256 + threadIdx.x;
        if (e < NE) {
            int pos = atomicAdd(&curu[__ldg(ei_i2u + NE + e)], 1);
            csr_i2u[pos] = __ldg(ei_i2u + e);
        }
    }
}

// ---------------- fused linear pair: out[n,COLS] = x[n,64] @ W[COLS,64]^T + b ----------------
template <int COLS>
__global__ void __launch_bounds__(256) linear_pair_kernel(
    const float* __restrict__ x0, const float* __restrict__ W0,
    const float* __restrict__ b0, float* __restrict__ out0, int n0, int nb0,
    const float* __restrict__ x1, const float* __restrict__ W1,
    const float* __restrict__ b1, float* __restrict__ out1, int n1)
{
    const float *x, *W, *bias; float* out; int n, row0;
    if (blockIdx.x < nb0) { x = x0; W = W0; bias = b0; out = out0; n = n0; row0 = blockIdx.x * 64; }
    else { x = x1; W = W1; bias = b1; out = out1; n = n1; row0 = (blockIdx.x - nb0) * 64; }

    constexpr int WS = COLS + 4;
    __shared__ float sW[64 * WS];
    __shared__ float sX[64 * 68];
    int tid = threadIdx.x;

    for (int i = tid; i < COLS * 64; i += 256) {
        int c = i >> 6, k = i & 63;
        sW[k * WS + c] = W[i];
    }
    for (int i = tid; i < 64 * 16; i += 256) {
        int r = i >> 4, q = i & 15;
        int row = row0 + r;
        float4 v = make_float4(0.f, 0.f, 0.f, 0.f);
        if (row < n) v = __ldg((const float4*)(x + (size_t)row * 64) + q);
        *(float4*)&sX[r * 68 + q * 4] = v;
    }
    __syncthreads();

    constexpr int CPT = COLS / 4;
    int r = tid >> 2, sub = tid & 3;
    int c0 = sub * CPT;
    float o[CPT];
    #pragma unroll
    for (int i = 0; i < CPT; i++) o[i] = __ldg(bias + c0 + i);

    #pragma unroll 4
    for (int k = 0; k < 64; k++) {
        float xv = sX[r * 68 + k];
        #pragma unroll
        for (int i = 0; i < CPT / 4; i++) {
            float4 w = *(const float4*)&sW[k * WS + c0 + 4 * i];
            o[4 * i + 0] += xv * w.x;
            o[4 * i + 1] += xv * w.y;
            o[4 * i + 2] += xv * w.z;
            o[4 * i + 3] += xv * w.w;
        }
    }
    int row = row0 + r;
    if (row < n) {
        #pragma unroll
        for (int i = 0; i < CPT / 4; i++) {
            float4 v = make_float4(o[4 * i], o[4 * i + 1], o[4 * i + 2], o[4 * i + 3]);
            ((float4*)(out + (size_t)row * COLS + c0))[i] = v;
        }
    }
}

// ---- GEMM-tiled fused conv: out = relu( mean @ Wrel^T + brel + h @ Wroot^T + h ) ----
// 64 rows/block, 128 threads. Phase A: 2 thr/row CSR gather -> sA (mean).
// Phase B: GEMM1 (sA x Wrel), reload sW<-Wroot / sA<-h, GEMM2, epilogue.
// 4 rows x 8 cols register tile per thread -> 2.67 FMA/LDS-byte (FFMA-bound).
__global__ void __launch_bounds__(128) combine_gemm_kernel(
    const float* __restrict__ feat, const float* __restrict__ h,
    const int* __restrict__ rs, const int* __restrict__ csr,
    const float* __restrict__ Wrel, const float* __restrict__ brel,
    const float* __restrict__ Wroot,
    float* __restrict__ out, int n)
{
    __shared__ float sW[64 * 68];   // 17408 B
    __shared__ float sA[64 * 68];   // 17408 B
    int tid = threadIdx.x;
    int row0 = blockIdx.x * 64;

    // load Wrel: W row-major [c][k] -> sW[k*68+c]
    for (int i = tid; i < 4096; i += 128) {
        int c = i >> 6, k = i & 63;
        sW[k * 68 + c] = __ldg(Wrel + i);
    }

    // phase A: gather mean. 2 threads per row, 32 floats each.
    {
        int r = tid >> 1, half = tid & 1;
        int row = row0 + r;
        bool valid = row < n;
        int e0 = valid ? __ldg(rs + row) : 0;
        int e1 = valid ? __ldg(rs + row + 1) : 0;
        float acc[32];
        #pragma unroll
        for (int i = 0; i < 32; i++) acc[i] = 0.f;
        for (int e = e0; e < e1; e++) {
            int s = __ldg(csr + e);
            const float4* p = (const float4*)(feat + (size_t)s * 64) + half * 8;
            #pragma unroll
            for (int j = 0; j < 8; j++) {
                float4 v = __ldg(p + j);
                acc[4 * j + 0] += v.x;  acc[4 * j + 1] += v.y;
                acc[4 * j + 2] += v.z;  acc[4 * j + 3] += v.w;
            }
        }
        float id = 1.f / fmaxf((float)(e1 - e0), 1.f);
        float* dst = &sA[r * 68 + half * 32];
        #pragma unroll
        for (int j = 0; j < 8; j++) {
            float4 v = make_float4(acc[4 * j] * id, acc[4 * j + 1] * id,
                                   acc[4 * j + 2] * id, acc[4 * j + 3] * id);
            *(float4*)(dst + 4 * j) = v;
        }
    }
    __syncthreads();

    // register tile: rows ro..ro+3, cols c0..c0+7
    int rg = tid >> 3, cg = tid & 7;
    int ro = rg * 4, c0 = cg * 8;
    float o[32];
    {
        float4 b0 = __ldg((const float4*)(brel + c0));
        float4 b1 = __ldg((const float4*)(brel + c0) + 1);
        #pragma unroll
        for (int i = 0; i < 4; i++) {
            o[8 * i + 0] = b0.x;  o[8 * i + 1] = b0.y;
            o[8 * i + 2] = b0.z;  o[8 * i + 3] = b0.w;
            o[8 * i + 4] = b1.x;  o[8 * i + 5] = b1.y;
            o[8 * i + 6] = b1.z;  o[8 * i + 7] = b1.w;
        }
    }

    // GEMM1: o += mean @ Wrel^T
    #pragma unroll 4
    for (int k = 0; k < 64; k++) {
        float4 w0 = *(const float4*)&sW[k * 68 + c0];
        float4 w1 = *(const float4*)&sW[k * 68 + c0 + 4];
        #pragma unroll
        for (int i = 0; i < 4; i++) {
            float a = sA[(ro + i) * 68 + k];
            o[8 * i + 0] += a * w0.x;  o[8 * i + 1] += a * w0.y;
            o[8 * i + 2] += a * w0.z;  o[8 * i + 3] += a * w0.w;
            o[8 * i + 4] += a * w1.x;  o[8 * i + 5] += a * w1.y;
            o[8 * i + 6] += a * w1.z;  o[8 * i + 7] += a * w1.w;
        }
    }
    __syncthreads();

    // reload: sW <- Wroot, sA <- h
    for (int i = tid; i < 4096; i += 128) {
        int c = i >> 6, k = i & 63;
        sW[k * 68 + c] = __ldg(Wroot + i);
    }
    {
        int r = tid >> 1, half = tid & 1;
        int row = row0 + r;
        bool valid = row < n;
        int rr = valid ? row : 0;
        const float4* hp = (const float4*)(h + (size_t)rr * 64) + half * 8;
        float* dst = &sA[r * 68 + half * 32];
        #pragma unroll
        for (int j = 0; j < 8; j++) {
            float4 v = valid ? __ldg(hp + j) : make_float4(0.f, 0.f, 0.f, 0.f);
            *(float4*)(dst + 4 * j) = v;
        }
    }
    __syncthreads();

    // GEMM2: o += h @ Wroot^T
    #pragma unroll 4
    for (int k = 0; k < 64; k++) {
        float4 w0 = *(const float4*)&sW[k * 68 + c0];
        float4 w1 = *(const float4*)&sW[k * 68 + c0 + 4];
        #pragma unroll
        for (int i = 0; i < 4; i++) {
            float a = sA[(ro + i) * 68 + k];
            o[8 * i + 0] += a * w0.x;  o[8 * i + 1] += a * w0.y;
            o[8 * i + 2] += a * w0.z;  o[8 * i + 3] += a * w0.w;
            o[8 * i + 4] += a * w1.x;  o[8 * i + 5] += a * w1.y;
            o[8 * i + 6] += a * w1.z;  o[8 * i + 7] += a * w1.w;
        }
    }

    // epilogue: + skip(h) -> relu -> store
    #pragma unroll
    for (int i = 0; i < 4; i++) {
        int row = row0 + ro + i;
        if (row < n) {
            float4 s0 = *(const float4*)&sA[(ro + i) * 68 + c0];
            float4 s1 = *(const float4*)&sA[(ro + i) * 68 + c0 + 4];
            float4 v0, v1;
            v0.x = fmaxf(o[8 * i + 0] + s0.x, 0.f);
            v0.y = fmaxf(o[8 * i + 1] + s0.y, 0.f);
            v0.z = fmaxf(o[8 * i + 2] + s0.z, 0.f);
            v0.w = fmaxf(o[8 * i + 3] + s0.w, 0.f);
            v1.x = fmaxf(o[8 * i + 4] + s1.x, 0.f);
            v1.y = fmaxf(o[8 * i + 5] + s1.y, 0.f);
            v1.z = fmaxf(o[8 * i + 6] + s1.z, 0.f);
            v1.w = fmaxf(o[8 * i + 7] + s1.w, 0.f);
            float4* op = (float4*)(out + (size_t)row * 64 + c0);
            op[0] = v0;
            op[1] = v1;
        }
    }
}

// ---------------- host ----------------
extern "C" void kernel_launch(void* const* d_in, const int* in_sizes, int n_in,
                              void* d_out, int out_size)
{
    const float* x_user = (const float*)d_in[0];
    const float* x_item = (const float*)d_in[1];
    const int*   ei_u2i = (const int*)d_in[2];
    const int*   ei_i2u = (const int*)d_in[3];
    const float* pre_w_u = (const float*)d_in[4];
    const float* pre_b_u = (const float*)d_in[5];
    const float* pre_w_i = (const float*)d_in[6];
    const float* pre_b_i = (const float*)d_in[7];
    const float* c1u2i_wrel  = (const float*)d_in[8];
    const float* c1u2i_brel  = (const float*)d_in[9];
    const float* c1u2i_wroot = (const float*)d_in[10];
    const float* c1i2u_wrel  = (const float*)d_in[11];
    const float* c1i2u_brel  = (const float*)d_in[12];
    const float* c1i2u_wroot = (const float*)d_in[13];
    const float* c2u2i_wrel  = (const float*)d_in[14];
    const float* c2u2i_brel  = (const float*)d_in[15];
    const float* c2u2i_wroot = (const float*)d_in[16];
    const float* c2i2u_wrel  = (const float*)d_in[17];
    const float* c2i2u_brel  = (const float*)d_in[18];
    const float* c2i2u_wroot = (const float*)d_in[19];
    const float* post_w_u = (const float*)d_in[20];
    const float* post_b_u = (const float*)d_in[21];
    const float* post_w_i = (const float*)d_in[22];
    const float* post_b_i = (const float*)d_in[23];
    float* out_u = (float*)d_out;
    float* out_i = out_u + (size_t)NU * OD;

    float *hu, *hi, *x1u, *x1i;
    int *csr_u2i, *csr_i2u, *rsu, *rsi, *curu, *curi, *partU, *partI;
    cudaGetSymbolAddress((void**)&hu,  g_hu);
    cudaGetSymbolAddress((void**)&hi,  g_hi);
    cudaGetSymbolAddress((void**)&x1u, g_x1u);
    cudaGetSymbolAddress((void**)&x1i, g_x1i);
    cudaGetSymbolAddress((void**)&csr_u2i, g_csr_u2i);
    cudaGetSymbolAddress((void**)&csr_i2u, g_csr_i2u);
    cudaGetSymbolAddress((void**)&rsu,  g_rsu);
    cudaGetSymbolAddress((void**)&rsi,  g_rsi);
    cudaGetSymbolAddress((void**)&curu, g_curu);
    cudaGetSymbolAddress((void**)&curi, g_curi);
    cudaGetSymbolAddress((void**)&partU, g_partU);
    cudaGetSymbolAddress((void**)&partI, g_partI);

    const int EB = (NE + 255) / 256;
    const int NUB64 = (NU + 63) / 64, NIB64 = (NI + 63) / 64;
    const int NBLKI = (NI + CHUNK - 1) / CHUNK;   // 98
    const int NBLKU = (NU + CHUNK - 1) / CHUNK;   // 196

    // CSR build (6 launches)
    zero_both_kernel<<<(NU + NI + 255) / 256, 256>>>(curu, curi);
    hist_both_kernel<<<2 * EB, 256>>>(ei_u2i, ei_i2u, curi, curu, EB);
    chunk_both_kernel<<<NBLKI + NBLKU, 256>>>(curi, partI, NBLKI, curu, partU);
    scan_parts_kernel<<<1, 256>>>(partI, NBLKI, partU, NBLKU);
    scanwrite_both_kernel<<<NBLKI + NBLKU, 256>>>(curi, partI, rsi, NBLKI, curu, partU, rsu);
    fill_both_kernel<<<2 * EB, 256>>>(ei_u2i, ei_i2u, curi, curu, csr_u2i, csr_i2u, EB);

    // preprocess linears
    linear_pair_kernel<64><<<NUB64 + NIB64, 256>>>(x_user, pre_w_u, pre_b_u, hu, NU, NUB64,
                                                   x_item, pre_w_i, pre_b_i, hi, NI);
    // layer 1
    combine_gemm_kernel<<<NIB64, 128>>>(hu, hi, rsi, csr_u2i,
                                        c1u2i_wrel, c1u2i_brel, c1u2i_wroot, x1i, NI);
    combine_gemm_kernel<<<NUB64, 128>>>(hi, hu, rsu, csr_i2u,
                                        c1i2u_wrel, c1i2u_brel, c1i2u_wroot, x1u, NU);
    // layer 2 (outputs overwrite pre-linear buffers)
    combine_gemm_kernel<<<NIB64, 128>>>(x1u, x1i, rsi, csr_u2i,
                                        c2u2i_wrel, c2u2i_brel, c2u2i_wroot, hi, NI);
    combine_gemm_kernel<<<NUB64, 128>>>(x1i, x1u, rsu, csr_i2u,
                                        c2i2u_wrel, c2i2u_brel, c2i2u_wroot, hu, NU);
    // postprocess linears -> output
    linear_pair_kernel<32><<<NUB64 + NIB64, 256>>>(hu, post_w_u, post_b_u, out_u, NU, NUB64,
                                                   hi, post_w_i, post_b_i, out_i, NI);
}